// round 7
// baseline (speedup 1.0000x reference)
#include <cuda_runtime.h>

#define NN 768
#define FD 64
#define DE 32
#define HD 64
#define H2 128

typedef unsigned long long u64;

// Scratch (allocation-free rule: __device__ globals), 16B-aligned
__device__ __align__(16) float g_P [NN * HD];
__device__ __align__(16) float g_Q [NN * HD];
__device__ __align__(16) float g_X1[NN * HD];
__device__ __align__(16) float g_X2[NN * HD];
__device__ unsigned g_cnt;          // zero-init at load; reset by final_kernel
__device__ unsigned g_edges[NN * NN];

// ---- packed f32x2 helpers (sm_103a) ----
__device__ __forceinline__ u64 pack2(float lo, float hi) {
    u64 r; asm("mov.b64 %0, {%1, %2};" : "=l"(r) : "f"(lo), "f"(hi)); return r;
}
__device__ __forceinline__ void unpack2(u64 v, float& lo, float& hi) {
    asm("mov.b64 {%0, %1}, %2;" : "=f"(lo), "=f"(hi) : "l"(v));
}
__device__ __forceinline__ u64 ffma2(u64 a, u64 b, u64 c) {
    u64 d; asm("fma.rn.f32x2 %0, %1, %2, %3;" : "=l"(d) : "l"(a), "l"(b), "l"(c));
    return d;
}
__device__ __forceinline__ u64 fadd2(u64 a, u64 b) {
    u64 d; asm("add.rn.f32x2 %0, %1, %2;" : "=l"(d) : "l"(a), "l"(b)); return d;
}

// Fused prep: (optional) adjacency compaction + P/Q GEMMs + zero next accumulator.
// P[i,h] = x_i @ (W[0:64]-W[64:128]) + ba ;  Q[j,h] = x_j @ W[64:128]
__global__ __launch_bounds__(256) void prep_kernel(
    const float* __restrict__ A,   // null => skip compaction
    const float* __restrict__ x, const float* __restrict__ W,
    const float* __restrict__ ba, float* __restrict__ P,
    float* __restrict__ Q, float* __restrict__ Xz)
{
    __shared__ float sW[2 * FD * HD];   // 32 KB
    __shared__ float sx[4][FD];
    __shared__ unsigned lcnt[4], lbase[4];

    const int tid = threadIdx.x;
    const int b   = blockIdx.x;
    const int nl  = tid >> 6;
    const int h   = tid & 63;
    const int node = b * 4 + nl;

    {
        unsigned g = b * 256u + (unsigned)tid;
        if (g < (NN * HD) / 4) ((float4*)Xz)[g] = make_float4(0.f, 0.f, 0.f, 0.f);
    }

    if (tid < 4) lcnt[tid] = 0;
    for (int k = tid; k < (2 * FD * HD) / 4; k += 256)
        ((float4*)sW)[k] = ((const float4*)W)[k];
    sx[nl][h] = x[node * FD + h];
    __syncthreads();

    unsigned myj[4][3]; int mc[4]; unsigned mpos[4];
    if (A) {
#pragma unroll
        for (int r = 0; r < 4; r++) {
            mc[r] = 0;
            const float* Ar = A + (size_t)(b * 4 + r) * NN;
#pragma unroll
            for (int t = 0; t < 3; t++) {
                int j = tid + t * 256;
                if (Ar[j] != 0.0f) myj[r][mc[r]++] = (unsigned)j;
            }
            mpos[r] = mc[r] ? atomicAdd(&lcnt[r], (unsigned)mc[r]) : 0u;
        }
    }

    float p = ba[h], q = 0.f;
#pragma unroll
    for (int f = 0; f < FD; f++) {
        float xv = sx[nl][f];
        float wi = sW[f * HD + h];
        float wd = sW[(FD + f) * HD + h];
        p = fmaf(xv, wi - wd, p);
        q = fmaf(xv, wd, q);
    }
    P[node * HD + h] = p;
    Q[node * HD + h] = q;

    if (A) {
        __syncthreads();
        if (tid == 0) {
#pragma unroll
            for (int r = 0; r < 4; r++)
                lbase[r] = atomicAdd(&g_cnt, lcnt[r]);
        }
        __syncthreads();
#pragma unroll
        for (int r = 0; r < 4; r++) {
            unsigned base = lbase[r] + mpos[r];
            unsigned rowbits = (unsigned)(b * 4 + r) << 10;
            for (int t = 0; t < mc[r]; t++)
                g_edges[base + t] = rowbits | myj[r][t];
        }
    }
}

// 4 lanes per edge (h-slice of 16), 8 edges per warp-task, packed f32x2 math.
// Per-lane arrays kept tiny (z2[8]/m2[8] u64, zf[16], ev[8]) to avoid spills.
__global__ __launch_bounds__(256, 2) void edge_kernel(
    const float* __restrict__ e,  const float* __restrict__ P,
    const float* __restrict__ Q,  const float* __restrict__ W,
    const float* __restrict__ Wb, const float* __restrict__ bb,
    float* __restrict__ out)
{
    __shared__ __align__(16) float sWe[DE * HD];   // 8 KB
    __shared__ __align__(16) float sWb[HD * HD];   // 16 KB
    __shared__ __align__(16) float sbb[HD];

    const int tid  = threadIdx.x;
    const int lane = tid & 31;
    const int warp = tid >> 5;
    const int sub  = lane & 3;          // h-quarter
    const int hbase = sub * 16;
    const int qbase = lane & 0x1C;      // first lane of this quad
    const unsigned FULL = 0xffffffffu;

    for (int k = tid; k < DE * HD; k += 256) sWe[k] = W[(2 * FD) * HD + k];
    for (int k = tid; k < HD * HD; k += 256) sWb[k] = Wb[k];
    if (tid < HD) sbb[tid] = bb[tid];
    __syncthreads();

    const unsigned cnt  = g_cnt;
    const unsigned nbat = (cnt + 7u) >> 3;           // 8 edges per task
    const unsigned slot   = (unsigned)warp * gridDim.x + blockIdx.x;
    const unsigned stride = gridDim.x * 8u;

    for (unsigned bat = slot; bat < nbat; bat += stride) {
        const unsigned eid = bat * 8u + (unsigned)(lane >> 2);
        const bool valid = (eid < cnt);
        const unsigned pk = g_edges[valid ? eid : (cnt - 1u)];
        const int i = (int)(pk >> 10);
        const int j = (int)(pk & 1023u);

        // this lane's 8-wide slice of the e-row (sub*8 .. sub*8+7)
        float ev[8];
        {
            const float4* ep = (const float4*)(e + ((size_t)(i * NN + j)) * DE + sub * 8);
            float4 v0 = ep[0], v1 = ep[1];
            ev[0] = v0.x; ev[1] = v0.y; ev[2] = v0.z; ev[3] = v0.w;
            ev[4] = v1.x; ev[5] = v1.y; ev[6] = v1.z; ev[7] = v1.w;
        }

        // z2 = P_i + Q_j on this lane's 16-wide h-slice (packed pairs)
        u64 z2[8];
        {
            const ulonglong2* Pp = (const ulonglong2*)(P + i * HD + hbase);
            const ulonglong2* Qp = (const ulonglong2*)(Q + j * HD + hbase);
#pragma unroll
            for (int c = 0; c < 4; c++) {
                ulonglong2 pv = Pp[c], qv = Qp[c];
                z2[c * 2 + 0] = fadd2(pv.x, qv.x);
                z2[c * 2 + 1] = fadd2(pv.y, qv.y);
            }
        }

        // layer a: z2 += e @ We ; e[de] broadcast from owner lane in the quad
#pragma unroll
        for (int de = 0; de < DE; de++) {
            const float evv = __shfl_sync(FULL, ev[de & 7], qbase | (de >> 3));
            const u64 evd = pack2(evv, evv);
            const ulonglong2* wr = (const ulonglong2*)(sWe + de * HD + hbase);
#pragma unroll
            for (int c = 0; c < 4; c++) {
                ulonglong2 w = wr[c];
                z2[c * 2 + 0] = ffma2(evd, w.x, z2[c * 2 + 0]);
                z2[c * 2 + 1] = ffma2(evd, w.y, z2[c * 2 + 1]);
            }
        }

        // relu -> scalar slice zf[16] (z2 dead after this)
        float zf[16];
#pragma unroll
        for (int c = 0; c < 8; c++) {
            float lo, hi; unpack2(z2[c], lo, hi);
            zf[c * 2 + 0] = fmaxf(lo, 0.f);
            zf[c * 2 + 1] = fmaxf(hi, 0.f);
        }

        // layer b: m = relu(z @ Wb + bb) on this lane's 16-wide slice
        u64 m2[8];
        {
            const ulonglong2* bp = (const ulonglong2*)(sbb + hbase);
#pragma unroll
            for (int c = 0; c < 4; c++) {
                ulonglong2 bv = bp[c];
                m2[c * 2 + 0] = bv.x;
                m2[c * 2 + 1] = bv.y;
            }
        }
#pragma unroll
        for (int k = 0; k < HD; k++) {
            const float zk = __shfl_sync(FULL, zf[k & 15], qbase | (k >> 4));
            const u64 zd = pack2(zk, zk);
            const ulonglong2* wr = (const ulonglong2*)(sWb + k * HD + hbase);
#pragma unroll
            for (int c = 0; c < 4; c++) {
                ulonglong2 w = wr[c];
                m2[c * 2 + 0] = ffma2(zd, w.x, m2[c * 2 + 0]);
                m2[c * 2 + 1] = ffma2(zd, w.y, m2[c * 2 + 1]);
            }
        }

        if (valid) {
            float4* op = (float4*)(out + i * HD + hbase);
#pragma unroll
            for (int c = 0; c < 4; c++) {
                float a0, a1, a2, a3;
                unpack2(m2[c * 2 + 0], a0, a1);
                unpack2(m2[c * 2 + 1], a2, a3);
                float4 v = make_float4(fmaxf(a0, 0.f), fmaxf(a1, 0.f),
                                       fmaxf(a2, 0.f), fmaxf(a3, 0.f));
                atomicAdd(op + c, v);
            }
        }
    }
}

// out[i] = sigmoid( relu(x2_i @ W3 + b3) @ W4 + b4 ); also resets g_cnt for
// the next graph replay (runs last; globals are zero-init for the first run).
__global__ __launch_bounds__(128) void final_kernel(
    const float* __restrict__ x,
    const float* __restrict__ W3, const float* __restrict__ b3,
    const float* __restrict__ W4, const float* __restrict__ b4,
    float* __restrict__ out)
{
    __shared__ float sx[HD];
    __shared__ float sred[H2];
    const int i = blockIdx.x, t = threadIdx.x;
    if (i == 0 && t == 0) g_cnt = 0;
    if (t < HD) sx[t] = x[i * HD + t];
    __syncthreads();

    float h = b3[t];
#pragma unroll
    for (int k = 0; k < HD; k++)
        h = fmaf(sx[k], W3[k * H2 + t], h);
    h = fmaxf(h, 0.f);

    sred[t] = h * W4[t];
    __syncthreads();
#pragma unroll
    for (int s = 64; s > 0; s >>= 1) {
        if (t < s) sred[t] += sred[t + s];
        __syncthreads();
    }
    if (t == 0) {
        float v = sred[0] + b4[0];
        out[i] = 1.0f / (1.0f + expf(-v));
    }
}

extern "C" void kernel_launch(void* const* d_in, const int* in_sizes, int n_in,
                              void* d_out, int out_size)
{
    const float* A   = (const float*)d_in[0];
    const float* x   = (const float*)d_in[1];
    const float* e   = (const float*)d_in[2];
    const float* W1a = (const float*)d_in[3];
    const float* b1a = (const float*)d_in[4];
    const float* W1b = (const float*)d_in[5];
    const float* b1b = (const float*)d_in[6];
    const float* W2a = (const float*)d_in[7];
    const float* b2a = (const float*)d_in[8];
    const float* W2b = (const float*)d_in[9];
    const float* b2b = (const float*)d_in[10];
    const float* W3  = (const float*)d_in[11];
    const float* b3  = (const float*)d_in[12];
    const float* W4  = (const float*)d_in[13];
    const float* b4  = (const float*)d_in[14];
    float* out = (float*)d_out;

    float *P, *Q, *X1, *X2;
    cudaGetSymbolAddress((void**)&P,  g_P);
    cudaGetSymbolAddress((void**)&Q,  g_Q);
    cudaGetSymbolAddress((void**)&X1, g_X1);
    cudaGetSymbolAddress((void**)&X2, g_X2);

    // Layer 1 (prep compacts A, computes P/Q, zeroes X1)
    prep_kernel<<<NN / 4, 256>>>(A, x, W1a, b1a, P, Q, X1);
    edge_kernel<<<296, 256>>>(e, P, Q, W1a, W1b, b1b, X1);
    // Layer 2 (no recompaction)
    prep_kernel<<<NN / 4, 256>>>(nullptr, X1, W2a, b2a, P, Q, X2);
    edge_kernel<<<296, 256>>>(e, P, Q, W2a, W2b, b2b, X2);
    // Head (also resets g_cnt)
    final_kernel<<<NN, H2>>>(X2, W3, b3, W4, b4, out);
}

// round 8
// speedup vs baseline: 1.7258x; 1.7258x over previous
#include <cuda_runtime.h>

#define NN 768
#define FD 64
#define DE 32
#define HD 64
#define H2 128
#define EGRID 296

typedef unsigned long long u64;

// Scratch (allocation-free rule: __device__ globals), 16B-aligned
__device__ __align__(16) float g_P [NN * HD];
__device__ __align__(16) float g_Q [NN * HD];
__device__ __align__(16) float g_X1[NN * HD];
__device__ __align__(16) float g_X2[NN * HD];
__device__ unsigned g_cnt;          // zero-init at load; reset by final_kernel
__device__ unsigned g_edges[NN * NN];

// ---- packed f32x2 helpers (sm_103a) ----
__device__ __forceinline__ u64 pack2(float lo, float hi) {
    u64 r; asm("mov.b64 %0, {%1, %2};" : "=l"(r) : "f"(lo), "f"(hi)); return r;
}
__device__ __forceinline__ void unpack2(u64 v, float& lo, float& hi) {
    asm("mov.b64 {%0, %1}, %2;" : "=f"(lo), "=f"(hi) : "l"(v));
}
__device__ __forceinline__ u64 ffma2(u64 a, u64 b, u64 c) {
    u64 d; asm("fma.rn.f32x2 %0, %1, %2, %3;" : "=l"(d) : "l"(a), "l"(b), "l"(c));
    return d;
}
__device__ __forceinline__ u64 fadd2(u64 a, u64 b) {
    u64 d; asm("add.rn.f32x2 %0, %1, %2;" : "=l"(d) : "l"(a), "l"(b)); return d;
}

// Fused prep: (optional) adjacency compaction + P/Q GEMMs + zero next accumulator.
// P[i,h] = x_i @ (W[0:64]-W[64:128]) + ba ;  Q[j,h] = x_j @ W[64:128]
__global__ __launch_bounds__(256) void prep_kernel(
    const float* __restrict__ A,   // null => skip compaction
    const float* __restrict__ x, const float* __restrict__ W,
    const float* __restrict__ ba, float* __restrict__ P,
    float* __restrict__ Q, float* __restrict__ Xz)
{
    __shared__ float sW[2 * FD * HD];   // 32 KB
    __shared__ float sx[4][FD];
    __shared__ unsigned lcnt[4], lbase[4];

    const int tid = threadIdx.x;
    const int b   = blockIdx.x;
    const int nl  = tid >> 6;
    const int h   = tid & 63;
    const int node = b * 4 + nl;

    {
        unsigned g = b * 256u + (unsigned)tid;
        if (g < (NN * HD) / 4) ((float4*)Xz)[g] = make_float4(0.f, 0.f, 0.f, 0.f);
    }

    if (tid < 4) lcnt[tid] = 0;
    for (int k = tid; k < (2 * FD * HD) / 4; k += 256)
        ((float4*)sW)[k] = ((const float4*)W)[k];
    sx[nl][h] = x[node * FD + h];
    __syncthreads();

    unsigned myj[4][3]; int mc[4]; unsigned mpos[4];
    if (A) {
#pragma unroll
        for (int r = 0; r < 4; r++) {
            mc[r] = 0;
            const float* Ar = A + (size_t)(b * 4 + r) * NN;
#pragma unroll
            for (int t = 0; t < 3; t++) {
                int j = tid + t * 256;
                if (Ar[j] != 0.0f) myj[r][mc[r]++] = (unsigned)j;
            }
            mpos[r] = mc[r] ? atomicAdd(&lcnt[r], (unsigned)mc[r]) : 0u;
        }
    }

    float p = ba[h], q = 0.f;
#pragma unroll
    for (int f = 0; f < FD; f++) {
        float xv = sx[nl][f];
        float wi = sW[f * HD + h];
        float wd = sW[(FD + f) * HD + h];
        p = fmaf(xv, wi - wd, p);
        q = fmaf(xv, wd, q);
    }
    P[node * HD + h] = p;
    Q[node * HD + h] = q;

    if (A) {
        __syncthreads();
        if (tid == 0) {
#pragma unroll
            for (int r = 0; r < 4; r++)
                lbase[r] = atomicAdd(&g_cnt, lcnt[r]);
        }
        __syncthreads();
#pragma unroll
        for (int r = 0; r < 4; r++) {
            unsigned base = lbase[r] + mpos[r];
            unsigned rowbits = (unsigned)(b * 4 + r) << 10;
            for (int t = 0; t < mc[r]; t++)
                g_edges[base + t] = rowbits | myj[r][t];
        }
    }
}

// Warp-pair per 32-edge batch: lane = edge, each warp of a pair owns a 32-wide
// h-half. Weight LDS are warp-uniform broadcasts; z-halves exchanged through a
// conflict-free [k][lane] smem tile; own-half z stays in registers.
// FFMA2 with <=16 live u64 accumulators (no spill regime).
__global__ __launch_bounds__(256, 2) void edge_kernel(
    const float* __restrict__ e,  const float* __restrict__ P,
    const float* __restrict__ Q,  const float* __restrict__ W,
    const float* __restrict__ Wb, const float* __restrict__ bb,
    float* __restrict__ out)
{
    extern __shared__ float sm[];
    float* sWe = sm;               // 2048 floats
    float* sWb = sm + 2048;        // 4096
    float* sbb = sm + 6144;        // 64
    float* zx  = sm + 6208;        // 4 pairs * 64k * 32lanes = 8192

    const int tid  = threadIdx.x;
    const int lane = tid & 31;
    const int warp = tid >> 5;
    const int pib  = warp >> 1;        // pair in block (0..3)
    const int hh   = warp & 1;         // h-half
    const int hbase = hh * 32;
    const int obase = (1 - hh) * 32;   // other half base
    const int barid = 1 + pib;

    for (int k = tid; k < DE * HD; k += 256) sWe[k] = W[(2 * FD) * HD + k];
    for (int k = tid; k < HD * HD; k += 256) sWb[k] = Wb[k];
    if (tid < HD) sbb[tid] = bb[tid];
    __syncthreads();

    const unsigned cnt  = g_cnt;
    const unsigned nbat = (cnt + 31u) >> 5;
    const unsigned pairG   = (unsigned)pib * gridDim.x + blockIdx.x;
    const unsigned npairs  = gridDim.x * 4u;
    float* zrow = zx + pib * (HD * 32);

    for (unsigned bat = pairG; bat < nbat; bat += npairs) {
        const unsigned eid = bat * 32u + (unsigned)lane;
        const bool valid = (eid < cnt);
        const unsigned pk = g_edges[valid ? eid : (cnt - 1u)];
        const int i = (int)(pk >> 10);
        const int j = (int)(pk & 1023u);

        // layer a accumulators (own h-half, packed): z2 = P_i + Q_j
        u64 z2[16];
        {
            const ulonglong2* Pp = (const ulonglong2*)(P + i * HD + hbase);
            const ulonglong2* Qp = (const ulonglong2*)(Q + j * HD + hbase);
#pragma unroll
            for (int c = 0; c < 8; c++) {
                ulonglong2 pv = Pp[c], qv = Qp[c];
                z2[c * 2 + 0] = fadd2(pv.x, qv.x);
                z2[c * 2 + 1] = fadd2(pv.y, qv.y);
            }
        }

        // layer a: z2 += e @ We ; e consumed in 4 chunks of 8 (own-lane values)
        const float* erow = e + ((size_t)(i * NN + j)) * DE;
#pragma unroll
        for (int chunk = 0; chunk < 4; chunk++) {
            float ev[8];
            {
                const float4* ep = (const float4*)(erow + chunk * 8);
                float4 v0 = ep[0], v1 = ep[1];
                ev[0] = v0.x; ev[1] = v0.y; ev[2] = v0.z; ev[3] = v0.w;
                ev[4] = v1.x; ev[5] = v1.y; ev[6] = v1.z; ev[7] = v1.w;
            }
#pragma unroll
            for (int d = 0; d < 8; d++) {
                const int de = chunk * 8 + d;
                const u64 evd = pack2(ev[d], ev[d]);
                const ulonglong2* wr = (const ulonglong2*)(sWe + de * HD + hbase);
#pragma unroll
                for (int c = 0; c < 8; c++) {
                    ulonglong2 w = wr[c];
                    z2[c * 2 + 0] = ffma2(evd, w.x, z2[c * 2 + 0]);
                    z2[c * 2 + 1] = ffma2(evd, w.y, z2[c * 2 + 1]);
                }
            }
        }

        // relu -> zf[32] (scalar; z2 dead afterwards)
        float zf[32];
#pragma unroll
        for (int c = 0; c < 16; c++) {
            float lo, hi; unpack2(z2[c], lo, hi);
            zf[c * 2 + 0] = fmaxf(lo, 0.f);
            zf[c * 2 + 1] = fmaxf(hi, 0.f);
        }

        // publish own z-half for the partner warp (conflict-free: bank = lane)
#pragma unroll
        for (int t = 0; t < 32; t++)
            zrow[(hbase + t) * 32 + lane] = zf[t];
        asm volatile("bar.sync %0, 64;" :: "r"(barid) : "memory");

        // layer b: m = relu(z @ Wb + bb) on own h-half
        u64 m2[16];
        {
            const ulonglong2* bp = (const ulonglong2*)(sbb + hbase);
#pragma unroll
            for (int c = 0; c < 8; c++) {
                ulonglong2 bv = bp[c];
                m2[c * 2 + 0] = bv.x;
                m2[c * 2 + 1] = bv.y;
            }
        }
        // own-half k: multiplier straight from registers
#pragma unroll
        for (int t = 0; t < 32; t++) {
            const u64 zd = pack2(zf[t], zf[t]);
            const ulonglong2* wr = (const ulonglong2*)(sWb + (hbase + t) * HD + hbase);
#pragma unroll
            for (int c = 0; c < 8; c++) {
                ulonglong2 w = wr[c];
                m2[c * 2 + 0] = ffma2(zd, w.x, m2[c * 2 + 0]);
                m2[c * 2 + 1] = ffma2(zd, w.y, m2[c * 2 + 1]);
            }
        }
        // other-half k: multiplier from partner's smem tile (1 wavefront LDS)
#pragma unroll
        for (int t = 0; t < 32; t++) {
            const float zk = zrow[(obase + t) * 32 + lane];
            const u64 zd = pack2(zk, zk);
            const ulonglong2* wr = (const ulonglong2*)(sWb + (obase + t) * HD + hbase);
#pragma unroll
            for (int c = 0; c < 8; c++) {
                ulonglong2 w = wr[c];
                m2[c * 2 + 0] = ffma2(zd, w.x, m2[c * 2 + 0]);
                m2[c * 2 + 1] = ffma2(zd, w.y, m2[c * 2 + 1]);
            }
        }

        if (valid) {
            float4* op = (float4*)(out + i * HD + hbase);
#pragma unroll
            for (int c = 0; c < 8; c++) {
                float a0, a1, a2, a3;
                unpack2(m2[c * 2 + 0], a0, a1);
                unpack2(m2[c * 2 + 1], a2, a3);
                float4 v = make_float4(fmaxf(a0, 0.f), fmaxf(a1, 0.f),
                                       fmaxf(a2, 0.f), fmaxf(a3, 0.f));
                atomicAdd(op + c, v);
            }
        }
        // partner must finish reading zx before next iteration overwrites it
        asm volatile("bar.sync %0, 64;" :: "r"(barid) : "memory");
    }
}

// out[i] = sigmoid( relu(x2_i @ W3 + b3) @ W4 + b4 ); also resets g_cnt for
// the next graph replay (runs last; globals are zero-init for the first run).
__global__ __launch_bounds__(128) void final_kernel(
    const float* __restrict__ x,
    const float* __restrict__ W3, const float* __restrict__ b3,
    const float* __restrict__ W4, const float* __restrict__ b4,
    float* __restrict__ out)
{
    __shared__ float sx[HD];
    __shared__ float sred[H2];
    const int i = blockIdx.x, t = threadIdx.x;
    if (i == 0 && t == 0) g_cnt = 0;
    if (t < HD) sx[t] = x[i * HD + t];
    __syncthreads();

    float h = b3[t];
#pragma unroll
    for (int k = 0; k < HD; k++)
        h = fmaf(sx[k], W3[k * H2 + t], h);
    h = fmaxf(h, 0.f);

    sred[t] = h * W4[t];
    __syncthreads();
#pragma unroll
    for (int s = 64; s > 0; s >>= 1) {
        if (t < s) sred[t] += sred[t + s];
        __syncthreads();
    }
    if (t == 0) {
        float v = sred[0] + b4[0];
        out[i] = 1.0f / (1.0f + expf(-v));
    }
}

extern "C" void kernel_launch(void* const* d_in, const int* in_sizes, int n_in,
                              void* d_out, int out_size)
{
    const float* A   = (const float*)d_in[0];
    const float* x   = (const float*)d_in[1];
    const float* e   = (const float*)d_in[2];
    const float* W1a = (const float*)d_in[3];
    const float* b1a = (const float*)d_in[4];
    const float* W1b = (const float*)d_in[5];
    const float* b1b = (const float*)d_in[6];
    const float* W2a = (const float*)d_in[7];
    const float* b2a = (const float*)d_in[8];
    const float* W2b = (const float*)d_in[9];
    const float* b2b = (const float*)d_in[10];
    const float* W3  = (const float*)d_in[11];
    const float* b3  = (const float*)d_in[12];
    const float* W4  = (const float*)d_in[13];
    const float* b4  = (const float*)d_in[14];
    float* out = (float*)d_out;

    float *P, *Q, *X1, *X2;
    cudaGetSymbolAddress((void**)&P,  g_P);
    cudaGetSymbolAddress((void**)&Q,  g_Q);
    cudaGetSymbolAddress((void**)&X1, g_X1);
    cudaGetSymbolAddress((void**)&X2, g_X2);

    const int SMEM = (2048 + 4096 + 64 + 4 * HD * 32) * 4;   // 57600 B
    cudaFuncSetAttribute(edge_kernel, cudaFuncAttributeMaxDynamicSharedMemorySize, SMEM);

    // Layer 1 (prep compacts A, computes P/Q, zeroes X1)
    prep_kernel<<<NN / 4, 256>>>(A, x, W1a, b1a, P, Q, X1);
    edge_kernel<<<EGRID, 256, SMEM>>>(e, P, Q, W1a, W1b, b1b, X1);
    // Layer 2 (no recompaction)
    prep_kernel<<<NN / 4, 256>>>(nullptr, X1, W2a, b2a, P, Q, X2);
    edge_kernel<<<EGRID, 256, SMEM>>>(e, P, Q, W2a, W2b, b2b, X2);
    // Head (also resets g_cnt)
    final_kernel<<<NN, H2>>>(X2, W3, b3, W4, b4, out);
}

// round 9
// speedup vs baseline: 1.8631x; 1.0795x over previous
#include <cuda_runtime.h>

#define NN 768
#define FD 64
#define DE 32
#define HD 64
#define H2 128
#define EGRID 232

typedef unsigned long long u64;

// Scratch (allocation-free rule: __device__ globals), 16B-aligned
__device__ __align__(16) float g_P [NN * HD];
__device__ __align__(16) float g_Q [NN * HD];
__device__ __align__(16) float g_X1[NN * HD];
__device__ __align__(16) float g_X2[NN * HD];
__device__ unsigned g_cnt;          // zero-init at load; reset by final_kernel
__device__ unsigned g_edges[NN * NN];

// ---- packed f32x2 helpers (sm_103a) ----
__device__ __forceinline__ u64 pack2(float lo, float hi) {
    u64 r; asm("mov.b64 %0, {%1, %2};" : "=l"(r) : "f"(lo), "f"(hi)); return r;
}
__device__ __forceinline__ void unpack2(u64 v, float& lo, float& hi) {
    asm("mov.b64 {%0, %1}, %2;" : "=f"(lo), "=f"(hi) : "l"(v));
}
__device__ __forceinline__ u64 ffma2(u64 a, u64 b, u64 c) {
    u64 d; asm("fma.rn.f32x2 %0, %1, %2, %3;" : "=l"(d) : "l"(a), "l"(b), "l"(c));
    return d;
}
__device__ __forceinline__ u64 fadd2(u64 a, u64 b) {
    u64 d; asm("add.rn.f32x2 %0, %1, %2;" : "=l"(d) : "l"(a), "l"(b)); return d;
}

// Fused prep: (optional) adjacency compaction + P/Q GEMMs + zero next accumulator.
// P[i,h] = x_i @ (W[0:64]-W[64:128]) + ba ;  Q[j,h] = x_j @ W[64:128]
__global__ __launch_bounds__(256) void prep_kernel(
    const float* __restrict__ A,   // null => skip compaction
    const float* __restrict__ x, const float* __restrict__ W,
    const float* __restrict__ ba, float* __restrict__ P,
    float* __restrict__ Q, float* __restrict__ Xz)
{
    __shared__ float sW[2 * FD * HD];   // 32 KB
    __shared__ float sx[4][FD];
    __shared__ unsigned lcnt[4], lbase[4];

    const int tid = threadIdx.x;
    const int b   = blockIdx.x;
    const int nl  = tid >> 6;
    const int h   = tid & 63;
    const int node = b * 4 + nl;

    {
        unsigned g = b * 256u + (unsigned)tid;
        if (g < (NN * HD) / 4) ((float4*)Xz)[g] = make_float4(0.f, 0.f, 0.f, 0.f);
    }

    if (tid < 4) lcnt[tid] = 0;
#pragma unroll
    for (int k = 0; k < 8; k++)
        ((float4*)sW)[tid + k * 256] = ((const float4*)W)[tid + k * 256];
    sx[nl][h] = x[node * FD + h];
    __syncthreads();

    unsigned myj[4][3]; int mc[4]; unsigned mpos[4];
    if (A) {
#pragma unroll
        for (int r = 0; r < 4; r++) {
            mc[r] = 0;
            const float* Ar = A + (size_t)(b * 4 + r) * NN;
#pragma unroll
            for (int t = 0; t < 3; t++) {
                int j = tid + t * 256;
                if (Ar[j] != 0.0f) myj[r][mc[r]++] = (unsigned)j;
            }
            mpos[r] = mc[r] ? atomicAdd(&lcnt[r], (unsigned)mc[r]) : 0u;
        }
    }

    float p = ba[h], q = 0.f;
#pragma unroll
    for (int f = 0; f < FD; f++) {
        float xv = sx[nl][f];
        float wi = sW[f * HD + h];
        float wd = sW[(FD + f) * HD + h];
        p = fmaf(xv, wi - wd, p);
        q = fmaf(xv, wd, q);
    }
    P[node * HD + h] = p;
    Q[node * HD + h] = q;

    if (A) {
        __syncthreads();
        if (tid == 0) {
#pragma unroll
            for (int r = 0; r < 4; r++)
                lbase[r] = atomicAdd(&g_cnt, lcnt[r]);
        }
        __syncthreads();
#pragma unroll
        for (int r = 0; r < 4; r++) {
            unsigned base = lbase[r] + mpos[r];
            unsigned rowbits = (unsigned)(b * 4 + r) << 10;
            for (int t = 0; t < mc[r]; t++)
                g_edges[base + t] = rowbits | myj[r][t];
        }
    }
}

// Warp-pair per 32-edge batch: lane = edge, each warp of a pair owns a 32-wide
// h-half. grid=232 -> 928 pairs >= ~922 batches: one task per pair, one wave.
__global__ __launch_bounds__(256, 2) void edge_kernel(
    const float* __restrict__ e,  const float* __restrict__ P,
    const float* __restrict__ Q,  const float* __restrict__ W,
    const float* __restrict__ Wb, const float* __restrict__ bb,
    float* __restrict__ out)
{
    extern __shared__ float sm[];
    float* sWe = sm;               // 2048 floats
    float* sWb = sm + 2048;        // 4096
    float* sbb = sm + 6144;        // 64
    float* zx  = sm + 6208;        // 4 pairs * 64k * 32lanes = 8192

    const int tid  = threadIdx.x;
    const int lane = tid & 31;
    const int warp = tid >> 5;
    const int pib  = warp >> 1;        // pair in block (0..3)
    const int hh   = warp & 1;         // h-half
    const int hbase = hh * 32;
    const int obase = (1 - hh) * 32;   // other half base
    const int barid = 1 + pib;

    // vectorized weight staging: 2048+4096 floats = 1536 float4 over 256 thr
    {
        const float4* Wg = (const float4*)(W + (2 * FD) * HD);
        ((float4*)sWe)[tid]       = Wg[tid];
        ((float4*)sWe)[tid + 256] = Wg[tid + 256];
        const float4* Wbg = (const float4*)Wb;
#pragma unroll
        for (int k = 0; k < 4; k++)
            ((float4*)sWb)[tid + k * 256] = Wbg[tid + k * 256];
        if (tid < HD) sbb[tid] = bb[tid];
    }
    __syncthreads();

    const unsigned cnt  = g_cnt;
    const unsigned nbat = (cnt + 31u) >> 5;
    const unsigned pairG   = (unsigned)pib * gridDim.x + blockIdx.x;
    const unsigned npairs  = gridDim.x * 4u;
    float* zrow = zx + pib * (HD * 32);

    for (unsigned bat = pairG; bat < nbat; bat += npairs) {
        // protect zx from previous iteration's partner reads (rare 2nd task)
        if (bat != pairG)
            asm volatile("bar.sync %0, 64;" :: "r"(barid) : "memory");

        const unsigned eid = bat * 32u + (unsigned)lane;
        const bool valid = (eid < cnt);
        const unsigned pk = g_edges[valid ? eid : (cnt - 1u)];
        const int i = (int)(pk >> 10);
        const int j = (int)(pk & 1023u);

        // layer a accumulators (own h-half, packed): z2 = P_i + Q_j
        u64 z2[16];
        {
            const ulonglong2* Pp = (const ulonglong2*)(P + i * HD + hbase);
            const ulonglong2* Qp = (const ulonglong2*)(Q + j * HD + hbase);
#pragma unroll
            for (int c = 0; c < 8; c++) {
                ulonglong2 pv = Pp[c], qv = Qp[c];
                z2[c * 2 + 0] = fadd2(pv.x, qv.x);
                z2[c * 2 + 1] = fadd2(pv.y, qv.y);
            }
        }

        // layer a: z2 += e @ We ; e consumed in 4 chunks of 8 (own-lane values)
        const float* erow = e + ((size_t)(i * NN + j)) * DE;
#pragma unroll
        for (int chunk = 0; chunk < 4; chunk++) {
            float ev[8];
            {
                const float4* ep = (const float4*)(erow + chunk * 8);
                float4 v0 = ep[0], v1 = ep[1];
                ev[0] = v0.x; ev[1] = v0.y; ev[2] = v0.z; ev[3] = v0.w;
                ev[4] = v1.x; ev[5] = v1.y; ev[6] = v1.z; ev[7] = v1.w;
            }
#pragma unroll
            for (int d = 0; d < 8; d++) {
                const int de = chunk * 8 + d;
                const u64 evd = pack2(ev[d], ev[d]);
                const ulonglong2* wr = (const ulonglong2*)(sWe + de * HD + hbase);
#pragma unroll
                for (int c = 0; c < 8; c++) {
                    ulonglong2 w = wr[c];
                    z2[c * 2 + 0] = ffma2(evd, w.x, z2[c * 2 + 0]);
                    z2[c * 2 + 1] = ffma2(evd, w.y, z2[c * 2 + 1]);
                }
            }
        }

        // relu -> zf[32] (scalar; z2 dead afterwards)
        float zf[32];
#pragma unroll
        for (int c = 0; c < 16; c++) {
            float lo, hi; unpack2(z2[c], lo, hi);
            zf[c * 2 + 0] = fmaxf(lo, 0.f);
            zf[c * 2 + 1] = fmaxf(hi, 0.f);
        }

        // publish own z-half for the partner warp (conflict-free: bank = lane)
#pragma unroll
        for (int t = 0; t < 32; t++)
            zrow[(hbase + t) * 32 + lane] = zf[t];
        asm volatile("bar.sync %0, 64;" :: "r"(barid) : "memory");

        // layer b: m = relu(z @ Wb + bb) on own h-half
        u64 m2[16];
        {
            const ulonglong2* bp = (const ulonglong2*)(sbb + hbase);
#pragma unroll
            for (int c = 0; c < 8; c++) {
                ulonglong2 bv = bp[c];
                m2[c * 2 + 0] = bv.x;
                m2[c * 2 + 1] = bv.y;
            }
        }
        // own-half k: multiplier straight from registers
#pragma unroll
        for (int t = 0; t < 32; t++) {
            const u64 zd = pack2(zf[t], zf[t]);
            const ulonglong2* wr = (const ulonglong2*)(sWb + (hbase + t) * HD + hbase);
#pragma unroll
            for (int c = 0; c < 8; c++) {
                ulonglong2 w = wr[c];
                m2[c * 2 + 0] = ffma2(zd, w.x, m2[c * 2 + 0]);
                m2[c * 2 + 1] = ffma2(zd, w.y, m2[c * 2 + 1]);
            }
        }
        // other-half k: multiplier from partner's smem tile (1 wavefront LDS)
#pragma unroll
        for (int t = 0; t < 32; t++) {
            const float zk = zrow[(obase + t) * 32 + lane];
            const u64 zd = pack2(zk, zk);
            const ulonglong2* wr = (const ulonglong2*)(sWb + (obase + t) * HD + hbase);
#pragma unroll
            for (int c = 0; c < 8; c++) {
                ulonglong2 w = wr[c];
                m2[c * 2 + 0] = ffma2(zd, w.x, m2[c * 2 + 0]);
                m2[c * 2 + 1] = ffma2(zd, w.y, m2[c * 2 + 1]);
            }
        }

        if (valid) {
            float4* op = (float4*)(out + i * HD + hbase);
#pragma unroll
            for (int c = 0; c < 8; c++) {
                float a0, a1, a2, a3;
                unpack2(m2[c * 2 + 0], a0, a1);
                unpack2(m2[c * 2 + 1], a2, a3);
                float4 v = make_float4(fmaxf(a0, 0.f), fmaxf(a1, 0.f),
                                       fmaxf(a2, 0.f), fmaxf(a3, 0.f));
                atomicAdd(op + c, v);
            }
        }
    }
}

// out[i] = sigmoid( relu(x2_i @ W3 + b3) @ W4 + b4 ); also resets g_cnt for
// the next graph replay (runs last; globals are zero-init for the first run).
__global__ __launch_bounds__(128) void final_kernel(
    const float* __restrict__ x,
    const float* __restrict__ W3, const float* __restrict__ b3,
    const float* __restrict__ W4, const float* __restrict__ b4,
    float* __restrict__ out)
{
    __shared__ float sx[HD];
    __shared__ float sred[H2];
    const int i = blockIdx.x, t = threadIdx.x;
    if (i == 0 && t == 0) g_cnt = 0;
    if (t < HD) sx[t] = x[i * HD + t];
    __syncthreads();

    float h = b3[t];
#pragma unroll
    for (int k = 0; k < HD; k++)
        h = fmaf(sx[k], W3[k * H2 + t], h);
    h = fmaxf(h, 0.f);

    sred[t] = h * W4[t];
    __syncthreads();
#pragma unroll
    for (int s = 64; s > 0; s >>= 1) {
        if (t < s) sred[t] += sred[t + s];
        __syncthreads();
    }
    if (t == 0) {
        float v = sred[0] + b4[0];
        out[i] = 1.0f / (1.0f + expf(-v));
    }
}

extern "C" void kernel_launch(void* const* d_in, const int* in_sizes, int n_in,
                              void* d_out, int out_size)
{
    const float* A   = (const float*)d_in[0];
    const float* x   = (const float*)d_in[1];
    const float* e   = (const float*)d_in[2];
    const float* W1a = (const float*)d_in[3];
    const float* b1a = (const float*)d_in[4];
    const float* W1b = (const float*)d_in[5];
    const float* b1b = (const float*)d_in[6];
    const float* W2a = (const float*)d_in[7];
    const float* b2a = (const float*)d_in[8];
    const float* W2b = (const float*)d_in[9];
    const float* b2b = (const float*)d_in[10];
    const float* W3  = (const float*)d_in[11];
    const float* b3  = (const float*)d_in[12];
    const float* W4  = (const float*)d_in[13];
    const float* b4  = (const float*)d_in[14];
    float* out = (float*)d_out;

    float *P, *Q, *X1, *X2;
    cudaGetSymbolAddress((void**)&P,  g_P);
    cudaGetSymbolAddress((void**)&Q,  g_Q);
    cudaGetSymbolAddress((void**)&X1, g_X1);
    cudaGetSymbolAddress((void**)&X2, g_X2);

    const int SMEM = (2048 + 4096 + 64 + 4 * HD * 32) * 4;   // 57600 B
    cudaFuncSetAttribute(edge_kernel, cudaFuncAttributeMaxDynamicSharedMemorySize, SMEM);

    // Layer 1 (prep compacts A, computes P/Q, zeroes X1)
    prep_kernel<<<NN / 4, 256>>>(A, x, W1a, b1a, P, Q, X1);
    edge_kernel<<<EGRID, 256, SMEM>>>(e, P, Q, W1a, W1b, b1b, X1);
    // Layer 2 (no recompaction)
    prep_kernel<<<NN / 4, 256>>>(nullptr, X1, W2a, b2a, P, Q, X2);
    edge_kernel<<<EGRID, 256, SMEM>>>(e, P, Q, W2a, W2b, b2b, X2);
    // Head (also resets g_cnt)
    final_kernel<<<NN, H2>>>(X2, W3, b3, W4, b4, out);
}

// round 10
// speedup vs baseline: 1.9085x; 1.0243x over previous
#include <cuda_runtime.h>

#define NN 768
#define FD 64
#define DE 32
#define HD 64
#define H2 128
#define EGRID 296

typedef unsigned long long u64;

// Scratch (allocation-free rule: __device__ globals), 16B-aligned
__device__ __align__(16) float g_P [NN * HD];
__device__ __align__(16) float g_Q [NN * HD];
__device__ __align__(16) float g_X1[NN * HD];
__device__ __align__(16) float g_X2[NN * HD];
__device__ unsigned g_cnt;          // zero-init at load; reset by final_kernel
__device__ unsigned g_edges[NN * NN];

// ---- packed f32x2 helpers (sm_103a) ----
__device__ __forceinline__ u64 pack2(float lo, float hi) {
    u64 r; asm("mov.b64 %0, {%1, %2};" : "=l"(r) : "f"(lo), "f"(hi)); return r;
}
__device__ __forceinline__ void unpack2(u64 v, float& lo, float& hi) {
    asm("mov.b64 {%0, %1}, %2;" : "=f"(lo), "=f"(hi) : "l"(v));
}
__device__ __forceinline__ u64 ffma2(u64 a, u64 b, u64 c) {
    u64 d; asm("fma.rn.f32x2 %0, %1, %2, %3;" : "=l"(d) : "l"(a), "l"(b), "l"(c));
    return d;
}
__device__ __forceinline__ u64 fadd2(u64 a, u64 b) {
    u64 d; asm("add.rn.f32x2 %0, %1, %2;" : "=l"(d) : "l"(a), "l"(b)); return d;
}

// Fused prep: (optional) adjacency compaction + P/Q GEMMs + zero next accumulator.
__global__ __launch_bounds__(256) void prep_kernel(
    const float* __restrict__ A,   // null => skip compaction
    const float* __restrict__ x, const float* __restrict__ W,
    const float* __restrict__ ba, float* __restrict__ P,
    float* __restrict__ Q, float* __restrict__ Xz)
{
    __shared__ float sW[2 * FD * HD];   // 32 KB
    __shared__ float sx[4][FD];
    __shared__ unsigned lcnt[4], lbase[4];

    const int tid = threadIdx.x;
    const int b   = blockIdx.x;
    const int nl  = tid >> 6;
    const int h   = tid & 63;
    const int node = b * 4 + nl;

    {
        unsigned g = b * 256u + (unsigned)tid;
        if (g < (NN * HD) / 4) ((float4*)Xz)[g] = make_float4(0.f, 0.f, 0.f, 0.f);
    }

    if (tid < 4) lcnt[tid] = 0;
#pragma unroll
    for (int k = 0; k < 8; k++)
        ((float4*)sW)[tid + k * 256] = ((const float4*)W)[tid + k * 256];
    sx[nl][h] = x[node * FD + h];
    __syncthreads();

    unsigned myj[4][3]; int mc[4]; unsigned mpos[4];
    if (A) {
#pragma unroll
        for (int r = 0; r < 4; r++) {
            mc[r] = 0;
            const float* Ar = A + (size_t)(b * 4 + r) * NN;
#pragma unroll
            for (int t = 0; t < 3; t++) {
                int j = tid + t * 256;
                if (Ar[j] != 0.0f) myj[r][mc[r]++] = (unsigned)j;
            }
            mpos[r] = mc[r] ? atomicAdd(&lcnt[r], (unsigned)mc[r]) : 0u;
        }
    }

    float p = ba[h], q = 0.f;
#pragma unroll
    for (int f = 0; f < FD; f++) {
        float xv = sx[nl][f];
        float wi = sW[f * HD + h];
        float wd = sW[(FD + f) * HD + h];
        p = fmaf(xv, wi - wd, p);
        q = fmaf(xv, wd, q);
    }
    P[node * HD + h] = p;
    Q[node * HD + h] = q;

    if (A) {
        __syncthreads();
        if (tid == 0) {
#pragma unroll
            for (int r = 0; r < 4; r++)
                lbase[r] = atomicAdd(&g_cnt, lcnt[r]);
        }
        __syncthreads();
#pragma unroll
        for (int r = 0; r < 4; r++) {
            unsigned base = lbase[r] + mpos[r];
            unsigned rowbits = (unsigned)(b * 4 + r) << 10;
            for (int t = 0; t < mc[r]; t++)
                g_edges[base + t] = rowbits | myj[r][t];
        }
    }
}

// Warp-pair per 32-edge batch; lane = edge, warp = 32-wide h-half.
// First batch's global gathers overlap the weight staging. z exchanged as
// packed u64 pairs; own-half layer-b runs before the pair barrier.
__global__ __launch_bounds__(256, 2) void edge_kernel(
    const float* __restrict__ e,  const float* __restrict__ P,
    const float* __restrict__ Q,  const float* __restrict__ W,
    const float* __restrict__ Wb, const float* __restrict__ bb,
    float* __restrict__ out)
{
    extern __shared__ float sm[];
    float* sWe = sm;               // 2048 floats
    float* sWb = sm + 2048;        // 4096
    float* sbb = sm + 6144;        // 64
    float* zx  = sm + 6208;        // 4 pairs * 1024 u64 = 8192 floats

    const int tid  = threadIdx.x;
    const int lane = tid & 31;
    const int warp = tid >> 5;
    const int pib  = warp >> 1;        // pair in block (0..3)
    const int hh   = warp & 1;         // h-half
    const int hbase = hh * 32;
    const int obase = (1 - hh) * 32;
    const int barid = 1 + pib;

    const unsigned cnt  = g_cnt;
    const unsigned nbat = (cnt + 31u) >> 5;
    const unsigned pairG  = (unsigned)pib * gridDim.x + blockIdx.x;
    const unsigned npairs = gridDim.x * 4u;
    u64* zrow = ((u64*)zx) + pib * 1024;

    // ---- prefetch first batch's gathers (before the staging sync) ----
    unsigned bat = pairG;
    bool have = bat < nbat;
    u64 pq[16];
    float ev[DE];
    bool valid = false;
    int i = 0;
    if (have) {
        const unsigned eid = bat * 32u + (unsigned)lane;
        valid = (eid < cnt);
        const unsigned pk = g_edges[valid ? eid : (cnt - 1u)];
        i = (int)(pk >> 10);
        const int j = (int)(pk & 1023u);
        const ulonglong2* Pp = (const ulonglong2*)(P + i * HD + hbase);
        const ulonglong2* Qp = (const ulonglong2*)(Q + j * HD + hbase);
#pragma unroll
        for (int c = 0; c < 8; c++) {
            ulonglong2 pv = Pp[c], qv = Qp[c];
            pq[c * 2 + 0] = fadd2(pv.x, qv.x);
            pq[c * 2 + 1] = fadd2(pv.y, qv.y);
        }
        const float4* ep = (const float4*)(e + ((size_t)(i * NN + j)) * DE);
#pragma unroll
        for (int q4 = 0; q4 < 8; q4++) {
            float4 v = ep[q4];
            ev[q4 * 4 + 0] = v.x; ev[q4 * 4 + 1] = v.y;
            ev[q4 * 4 + 2] = v.z; ev[q4 * 4 + 3] = v.w;
        }
    }

    // ---- weight staging (overlaps the gathers above) ----
    {
        const float4* Wg = (const float4*)(W + (2 * FD) * HD);
        ((float4*)sWe)[tid]       = Wg[tid];
        ((float4*)sWe)[tid + 256] = Wg[tid + 256];
        const float4* Wbg = (const float4*)Wb;
#pragma unroll
        for (int k = 0; k < 4; k++)
            ((float4*)sWb)[tid + k * 256] = Wbg[tid + k * 256];
        if (tid < HD) sbb[tid] = bb[tid];
    }
    __syncthreads();

    while (have) {
        // layer a: z2 = P_i + Q_j + e @ We  (own 32-wide h-half, packed)
        u64 z2[16];
#pragma unroll
        for (int c = 0; c < 16; c++) z2[c] = pq[c];
#pragma unroll
        for (int de = 0; de < DE; de++) {
            const u64 evd = pack2(ev[de], ev[de]);
            const ulonglong2* wr = (const ulonglong2*)(sWe + de * HD + hbase);
#pragma unroll
            for (int c = 0; c < 8; c++) {
                ulonglong2 w = wr[c];
                z2[c * 2 + 0] = ffma2(evd, w.x, z2[c * 2 + 0]);
                z2[c * 2 + 1] = ffma2(evd, w.y, z2[c * 2 + 1]);
            }
        }

        // relu packed in place
#pragma unroll
        for (int c = 0; c < 16; c++) {
            float lo, hi; unpack2(z2[c], lo, hi);
            z2[c] = pack2(fmaxf(lo, 0.f), fmaxf(hi, 0.f));
        }

        // publish own z-half as u64 pairs: slot [(hbase/2+c)*32 + lane]
#pragma unroll
        for (int c = 0; c < 16; c++)
            zrow[(hbase / 2 + c) * 32 + lane] = z2[c];

        // layer b (own-half k first — no barrier needed for these)
        u64 m2[16];
        {
            const ulonglong2* bp = (const ulonglong2*)(sbb + hbase);
#pragma unroll
            for (int c = 0; c < 8; c++) {
                ulonglong2 bv = bp[c];
                m2[c * 2 + 0] = bv.x;
                m2[c * 2 + 1] = bv.y;
            }
        }
#pragma unroll
        for (int c = 0; c < 16; c++) {
            float zk0, zk1; unpack2(z2[c], zk0, zk1);
            const u64 zd0 = pack2(zk0, zk0);
            const u64 zd1 = pack2(zk1, zk1);
            const ulonglong2* wr0 = (const ulonglong2*)(sWb + (hbase + 2 * c + 0) * HD + hbase);
            const ulonglong2* wr1 = (const ulonglong2*)(sWb + (hbase + 2 * c + 1) * HD + hbase);
#pragma unroll
            for (int q = 0; q < 8; q++) {
                ulonglong2 w0 = wr0[q];
                ulonglong2 w1 = wr1[q];
                m2[q * 2 + 0] = ffma2(zd0, w0.x, m2[q * 2 + 0]);
                m2[q * 2 + 1] = ffma2(zd0, w0.y, m2[q * 2 + 1]);
                m2[q * 2 + 0] = ffma2(zd1, w1.x, m2[q * 2 + 0]);
                m2[q * 2 + 1] = ffma2(zd1, w1.y, m2[q * 2 + 1]);
            }
        }

        // partner's z-half
        asm volatile("bar.sync %0, 64;" :: "r"(barid) : "memory");
#pragma unroll
        for (int c = 0; c < 16; c++) {
            const u64 zo = zrow[(obase / 2 + c) * 32 + lane];   // LDS.64
            float zk0, zk1; unpack2(zo, zk0, zk1);
            const u64 zd0 = pack2(zk0, zk0);
            const u64 zd1 = pack2(zk1, zk1);
            const ulonglong2* wr0 = (const ulonglong2*)(sWb + (obase + 2 * c + 0) * HD + hbase);
            const ulonglong2* wr1 = (const ulonglong2*)(sWb + (obase + 2 * c + 1) * HD + hbase);
#pragma unroll
            for (int q = 0; q < 8; q++) {
                ulonglong2 w0 = wr0[q];
                ulonglong2 w1 = wr1[q];
                m2[q * 2 + 0] = ffma2(zd0, w0.x, m2[q * 2 + 0]);
                m2[q * 2 + 1] = ffma2(zd0, w0.y, m2[q * 2 + 1]);
                m2[q * 2 + 0] = ffma2(zd1, w1.x, m2[q * 2 + 0]);
                m2[q * 2 + 1] = ffma2(zd1, w1.y, m2[q * 2 + 1]);
            }
        }

        if (valid) {
            float4* op = (float4*)(out + i * HD + hbase);
#pragma unroll
            for (int c = 0; c < 8; c++) {
                float a0, a1, a2, a3;
                unpack2(m2[c * 2 + 0], a0, a1);
                unpack2(m2[c * 2 + 1], a2, a3);
                float4 v = make_float4(fmaxf(a0, 0.f), fmaxf(a1, 0.f),
                                       fmaxf(a2, 0.f), fmaxf(a3, 0.f));
                atomicAdd(op + c, v);
            }
        }

        // advance (rare: >1 task per pair)
        bat += npairs;
        have = bat < nbat;
        if (have) {
            // partner must finish reading zrow before we overwrite it
            asm volatile("bar.sync %0, 64;" :: "r"(barid) : "memory");
            const unsigned eid = bat * 32u + (unsigned)lane;
            valid = (eid < cnt);
            const unsigned pk = g_edges[valid ? eid : (cnt - 1u)];
            i = (int)(pk >> 10);
            const int j = (int)(pk & 1023u);
            const ulonglong2* Pp = (const ulonglong2*)(P + i * HD + hbase);
            const ulonglong2* Qp = (const ulonglong2*)(Q + j * HD + hbase);
#pragma unroll
            for (int c = 0; c < 8; c++) {
                ulonglong2 pv = Pp[c], qv = Qp[c];
                pq[c * 2 + 0] = fadd2(pv.x, qv.x);
                pq[c * 2 + 1] = fadd2(pv.y, qv.y);
            }
            const float4* ep = (const float4*)(e + ((size_t)(i * NN + j)) * DE);
#pragma unroll
            for (int q4 = 0; q4 < 8; q4++) {
                float4 v = ep[q4];
                ev[q4 * 4 + 0] = v.x; ev[q4 * 4 + 1] = v.y;
                ev[q4 * 4 + 2] = v.z; ev[q4 * 4 + 3] = v.w;
            }
        }
    }
}

// out[i] = sigmoid( relu(x2_i @ W3 + b3) @ W4 + b4 ); resets g_cnt (runs last).
__global__ __launch_bounds__(128) void final_kernel(
    const float* __restrict__ x,
    const float* __restrict__ W3, const float* __restrict__ b3,
    const float* __restrict__ W4, const float* __restrict__ b4,
    float* __restrict__ out)
{
    __shared__ float sx[HD];
    __shared__ float sred[H2];
    const int i = blockIdx.x, t = threadIdx.x;
    if (i == 0 && t == 0) g_cnt = 0;
    if (t < HD) sx[t] = x[i * HD + t];
    __syncthreads();

    float h = b3[t];
#pragma unroll
    for (int k = 0; k < HD; k++)
        h = fmaf(sx[k], W3[k * H2 + t], h);
    h = fmaxf(h, 0.f);

    sred[t] = h * W4[t];
    __syncthreads();
#pragma unroll
    for (int s = 64; s > 0; s >>= 1) {
        if (t < s) sred[t] += sred[t + s];
        __syncthreads();
    }
    if (t == 0) {
        float v = sred[0] + b4[0];
        out[i] = 1.0f / (1.0f + expf(-v));
    }
}

extern "C" void kernel_launch(void* const* d_in, const int* in_sizes, int n_in,
                              void* d_out, int out_size)
{
    const float* A   = (const float*)d_in[0];
    const float* x   = (const float*)d_in[1];
    const float* e   = (const float*)d_in[2];
    const float* W1a = (const float*)d_in[3];
    const float* b1a = (const float*)d_in[4];
    const float* W1b = (const float*)d_in[5];
    const float* b1b = (const float*)d_in[6];
    const float* W2a = (const float*)d_in[7];
    const float* b2a = (const float*)d_in[8];
    const float* W2b = (const float*)d_in[9];
    const float* b2b = (const float*)d_in[10];
    const float* W3  = (const float*)d_in[11];
    const float* b3  = (const float*)d_in[12];
    const float* W4  = (const float*)d_in[13];
    const float* b4  = (const float*)d_in[14];
    float* out = (float*)d_out;

    float *P, *Q, *X1, *X2;
    cudaGetSymbolAddress((void**)&P,  g_P);
    cudaGetSymbolAddress((void**)&Q,  g_Q);
    cudaGetSymbolAddress((void**)&X1, g_X1);
    cudaGetSymbolAddress((void**)&X2, g_X2);

    const int SMEM = (2048 + 4096 + 64 + 4 * HD * 32) * 4;   // 57600 B
    cudaFuncSetAttribute(edge_kernel, cudaFuncAttributeMaxDynamicSharedMemorySize, SMEM);

    // Layer 1 (prep compacts A, computes P/Q, zeroes X1)
    prep_kernel<<<NN / 4, 256>>>(A, x, W1a, b1a, P, Q, X1);
    edge_kernel<<<EGRID, 256, SMEM>>>(e, P, Q, W1a, W1b, b1b, X1);
    // Layer 2 (no recompaction)
    prep_kernel<<<NN / 4, 256>>>(nullptr, X1, W2a, b2a, P, Q, X2);
    edge_kernel<<<EGRID, 256, SMEM>>>(e, P, Q, W2a, W2b, b2b, X2);
    // Head (also resets g_cnt)
    final_kernel<<<NN, H2>>>(X2, W3, b3, W4, b4, out);
}

// round 11
// speedup vs baseline: 2.3122x; 1.2115x over previous
#include <cuda_runtime.h>

#define NN 768
#define FD 64
#define DE 32
#define HD 64
#define H2 128
#define EGRID 296

typedef unsigned long long u64;

// Scratch (allocation-free rule: __device__ globals), 16B-aligned
__device__ __align__(16) float g_P [NN * HD];
__device__ __align__(16) float g_Q [NN * HD];
__device__ __align__(16) float g_X1[NN * HD];
__device__ __align__(16) float g_X2[NN * HD];
__device__ unsigned g_cnt;          // zero-init at load; reset by final_kernel
__device__ unsigned g_edges[NN * NN];

// ---- packed f32x2 helpers (sm_103a) ----
__device__ __forceinline__ u64 pack2(float lo, float hi) {
    u64 r; asm("mov.b64 %0, {%1, %2};" : "=l"(r) : "f"(lo), "f"(hi)); return r;
}
__device__ __forceinline__ void unpack2(u64 v, float& lo, float& hi) {
    asm("mov.b64 {%0, %1}, %2;" : "=f"(lo), "=f"(hi) : "l"(v));
}
__device__ __forceinline__ u64 ffma2(u64 a, u64 b, u64 c) {
    u64 d; asm("fma.rn.f32x2 %0, %1, %2, %3;" : "=l"(d) : "l"(a), "l"(b), "l"(c));
    return d;
}
__device__ __forceinline__ u64 fadd2(u64 a, u64 b) {
    u64 d; asm("add.rn.f32x2 %0, %1, %2;" : "=l"(d) : "l"(a), "l"(b)); return d;
}

// Fused prep: (optional) adjacency compaction + P/Q GEMMs + zero next accumulator.
__global__ __launch_bounds__(256) void prep_kernel(
    const float* __restrict__ A,   // null => skip compaction
    const float* __restrict__ x, const float* __restrict__ W,
    const float* __restrict__ ba, float* __restrict__ P,
    float* __restrict__ Q, float* __restrict__ Xz)
{
    __shared__ float sW[2 * FD * HD];   // 32 KB
    __shared__ float sx[4][FD];
    __shared__ unsigned lcnt[4], lbase[4];

    const int tid = threadIdx.x;
    const int b   = blockIdx.x;
    const int nl  = tid >> 6;
    const int h   = tid & 63;
    const int node = b * 4 + nl;

    {
        unsigned g = b * 256u + (unsigned)tid;
        if (g < (NN * HD) / 4) ((float4*)Xz)[g] = make_float4(0.f, 0.f, 0.f, 0.f);
    }

    if (tid < 4) lcnt[tid] = 0;
#pragma unroll
    for (int k = 0; k < 8; k++)
        ((float4*)sW)[tid + k * 256] = ((const float4*)W)[tid + k * 256];
    sx[nl][h] = x[node * FD + h];
    __syncthreads();

    unsigned myj[4][3]; int mc[4]; unsigned mpos[4];
    if (A) {
#pragma unroll
        for (int r = 0; r < 4; r++) {
            mc[r] = 0;
            const float* Ar = A + (size_t)(b * 4 + r) * NN;
#pragma unroll
            for (int t = 0; t < 3; t++) {
                int j = tid + t * 256;
                if (Ar[j] != 0.0f) myj[r][mc[r]++] = (unsigned)j;
            }
            mpos[r] = mc[r] ? atomicAdd(&lcnt[r], (unsigned)mc[r]) : 0u;
        }
    }

    float p = ba[h], q = 0.f;
#pragma unroll
    for (int f = 0; f < FD; f++) {
        float xv = sx[nl][f];
        float wi = sW[f * HD + h];
        float wd = sW[(FD + f) * HD + h];
        p = fmaf(xv, wi - wd, p);
        q = fmaf(xv, wd, q);
    }
    P[node * HD + h] = p;
    Q[node * HD + h] = q;

    if (A) {
        __syncthreads();
        if (tid == 0) {
#pragma unroll
            for (int r = 0; r < 4; r++)
                lbase[r] = atomicAdd(&g_cnt, lcnt[r]);
        }
        __syncthreads();
#pragma unroll
        for (int r = 0; r < 4; r++) {
            unsigned base = lbase[r] + mpos[r];
            unsigned rowbits = (unsigned)(b * 4 + r) << 10;
            for (int t = 0; t < mc[r]; t++)
                g_edges[base + t] = rowbits | myj[r][t];
        }
    }
}

// Warp-pair per 32-edge batch. Layer-a: lane = edge, own 32-h half, uniform
// weight LDS. Layer-b retiled: z staged to smem [k][edge]; lane = (edge-group
// of 4, h-group of 8) so weight & z LDS are lane-divergent (1 wavefront each).
__global__ __launch_bounds__(256, 2) void edge_kernel(
    const float* __restrict__ e,  const float* __restrict__ P,
    const float* __restrict__ Q,  const float* __restrict__ W,
    const float* __restrict__ Wb, const float* __restrict__ bb,
    float* __restrict__ out)
{
    extern __shared__ float sm[];
    float* sWe = sm;               // 2048 floats
    float* sWb = sm + 2048;        // 4096
    float* sbb = sm + 6144;        // 64
    float* zx  = sm + 6208;        // 4 pairs * [64][32] floats = 8192

    const int tid  = threadIdx.x;
    const int lane = tid & 31;
    const int warp = tid >> 5;
    const int pib  = warp >> 1;        // pair in block (0..3)
    const int hh   = warp & 1;         // h-half
    const int hbase = hh * 32;
    const int barid = 1 + pib;
    // layer-b tile coords
    const int eg   = lane >> 2;        // edge group of 4 (0..7)
    const int hg   = lane & 3;         // h group of 8 (0..3)
    const int hoff = hbase + hg * 8;

    const unsigned cnt  = g_cnt;
    const unsigned nbat = (cnt + 31u) >> 5;
    const unsigned pairG  = (unsigned)pib * gridDim.x + blockIdx.x;
    const unsigned npairs = gridDim.x * 4u;
    float* zs = zx + pib * (HD * 32);   // [k][edge] tile for this pair

    // ---- prefetch first batch's gathers (before the staging sync) ----
    unsigned bat = pairG;
    bool have = bat < nbat;
    u64 pq[16];
    float ev[DE];
    int i = 0;
    if (have) {
        const unsigned eid = bat * 32u + (unsigned)lane;
        const unsigned pk = g_edges[(eid < cnt) ? eid : (cnt - 1u)];
        i = (int)(pk >> 10);
        const int j = (int)(pk & 1023u);
        const ulonglong2* Pp = (const ulonglong2*)(P + i * HD + hbase);
        const ulonglong2* Qp = (const ulonglong2*)(Q + j * HD + hbase);
#pragma unroll
        for (int c = 0; c < 8; c++) {
            ulonglong2 pv = Pp[c], qv = Qp[c];
            pq[c * 2 + 0] = fadd2(pv.x, qv.x);
            pq[c * 2 + 1] = fadd2(pv.y, qv.y);
        }
        const float4* ep = (const float4*)(e + ((size_t)(i * NN + j)) * DE);
#pragma unroll
        for (int q4 = 0; q4 < 8; q4++) {
            float4 v = ep[q4];
            ev[q4 * 4 + 0] = v.x; ev[q4 * 4 + 1] = v.y;
            ev[q4 * 4 + 2] = v.z; ev[q4 * 4 + 3] = v.w;
        }
    }

    // ---- weight staging (overlaps the gathers above) ----
    {
        const float4* Wg = (const float4*)(W + (2 * FD) * HD);
        ((float4*)sWe)[tid]       = Wg[tid];
        ((float4*)sWe)[tid + 256] = Wg[tid + 256];
        const float4* Wbg = (const float4*)Wb;
#pragma unroll
        for (int k = 0; k < 4; k++)
            ((float4*)sWb)[tid + k * 256] = Wbg[tid + k * 256];
        if (tid < HD) sbb[tid] = bb[tid];
    }
    __syncthreads();

    while (have) {
        // ---- layer a (lane = edge, own 32-h half, packed) ----
        u64 z2[16];
#pragma unroll
        for (int c = 0; c < 16; c++) z2[c] = pq[c];
#pragma unroll
        for (int de = 0; de < DE; de++) {
            const u64 evd = pack2(ev[de], ev[de]);
            const ulonglong2* wr = (const ulonglong2*)(sWe + de * HD + hbase);
#pragma unroll
            for (int c = 0; c < 8; c++) {
                ulonglong2 w = wr[c];
                z2[c * 2 + 0] = ffma2(evd, w.x, z2[c * 2 + 0]);
                z2[c * 2 + 1] = ffma2(evd, w.y, z2[c * 2 + 1]);
            }
        }

        // relu + stage z as [k][edge] scalars (1 wavefront per STS)
#pragma unroll
        for (int c = 0; c < 16; c++) {
            float lo, hi; unpack2(z2[c], lo, hi);
            zs[(hbase + 2 * c + 0) * 32 + lane] = fmaxf(lo, 0.f);
            zs[(hbase + 2 * c + 1) * 32 + lane] = fmaxf(hi, 0.f);
        }
        asm volatile("bar.sync %0, 64;" :: "r"(barid) : "memory");

        // ---- layer b (lane = 4 edges x 8 h tile) ----
        u64 m2[16];
        {
            const ulonglong2* bp = (const ulonglong2*)(sbb + hoff);
            ulonglong2 b0 = bp[0], b1 = bp[1];
#pragma unroll
            for (int e4 = 0; e4 < 4; e4++) {
                m2[e4 * 4 + 0] = b0.x; m2[e4 * 4 + 1] = b0.y;
                m2[e4 * 4 + 2] = b1.x; m2[e4 * 4 + 3] = b1.y;
            }
        }
#pragma unroll 8
        for (int k = 0; k < HD; k++) {
            float4 z4 = *(const float4*)(zs + k * 32 + eg * 4);
            const ulonglong2* wp = (const ulonglong2*)(sWb + k * HD + hoff);
            ulonglong2 wA = wp[0], wB = wp[1];
            u64 zd;
            zd = pack2(z4.x, z4.x);
            m2[0]  = ffma2(zd, wA.x, m2[0]);  m2[1]  = ffma2(zd, wA.y, m2[1]);
            m2[2]  = ffma2(zd, wB.x, m2[2]);  m2[3]  = ffma2(zd, wB.y, m2[3]);
            zd = pack2(z4.y, z4.y);
            m2[4]  = ffma2(zd, wA.x, m2[4]);  m2[5]  = ffma2(zd, wA.y, m2[5]);
            m2[6]  = ffma2(zd, wB.x, m2[6]);  m2[7]  = ffma2(zd, wB.y, m2[7]);
            zd = pack2(z4.z, z4.z);
            m2[8]  = ffma2(zd, wA.x, m2[8]);  m2[9]  = ffma2(zd, wA.y, m2[9]);
            m2[10] = ffma2(zd, wB.x, m2[10]); m2[11] = ffma2(zd, wB.y, m2[11]);
            zd = pack2(z4.w, z4.w);
            m2[12] = ffma2(zd, wA.x, m2[12]); m2[13] = ffma2(zd, wA.y, m2[13]);
            m2[14] = ffma2(zd, wB.x, m2[14]); m2[15] = ffma2(zd, wB.y, m2[15]);
        }

        // ---- relu + scatter (4 edges x 8 h per lane) ----
#pragma unroll
        for (int e4 = 0; e4 < 4; e4++) {
            const int esel = eg * 4 + e4;
            const int ie = __shfl_sync(0xffffffffu, i, esel);
            const bool ve = (bat * 32u + (unsigned)esel) < cnt;
            if (ve) {
                float4* op = (float4*)(out + ie * HD + hoff);
                float a0, a1, a2, a3;
                unpack2(m2[e4 * 4 + 0], a0, a1);
                unpack2(m2[e4 * 4 + 1], a2, a3);
                atomicAdd(op, make_float4(fmaxf(a0, 0.f), fmaxf(a1, 0.f),
                                          fmaxf(a2, 0.f), fmaxf(a3, 0.f)));
                unpack2(m2[e4 * 4 + 2], a0, a1);
                unpack2(m2[e4 * 4 + 3], a2, a3);
                atomicAdd(op + 1, make_float4(fmaxf(a0, 0.f), fmaxf(a1, 0.f),
                                              fmaxf(a2, 0.f), fmaxf(a3, 0.f)));
            }
        }

        // ---- advance (rare: >1 task per pair) ----
        bat += npairs;
        have = bat < nbat;
        if (have) {
            asm volatile("bar.sync %0, 64;" :: "r"(barid) : "memory");
            const unsigned eid = bat * 32u + (unsigned)lane;
            const unsigned pk = g_edges[(eid < cnt) ? eid : (cnt - 1u)];
            i = (int)(pk >> 10);
            const int j = (int)(pk & 1023u);
            const ulonglong2* Pp = (const ulonglong2*)(P + i * HD + hbase);
            const ulonglong2* Qp = (const ulonglong2*)(Q + j * HD + hbase);
#pragma unroll
            for (int c = 0; c < 8; c++) {
                ulonglong2 pv = Pp[c], qv = Qp[c];
                pq[c * 2 + 0] = fadd2(pv.x, qv.x);
                pq[c * 2 + 1] = fadd2(pv.y, qv.y);
            }
            const float4* ep = (const float4*)(e + ((size_t)(i * NN + j)) * DE);
#pragma unroll
            for (int q4 = 0; q4 < 8; q4++) {
                float4 v = ep[q4];
                ev[q4 * 4 + 0] = v.x; ev[q4 * 4 + 1] = v.y;
                ev[q4 * 4 + 2] = v.z; ev[q4 * 4 + 3] = v.w;
            }
        }
    }
}

// out[i] = sigmoid( relu(x2_i @ W3 + b3) @ W4 + b4 ); resets g_cnt (runs last).
__global__ __launch_bounds__(128) void final_kernel(
    const float* __restrict__ x,
    const float* __restrict__ W3, const float* __restrict__ b3,
    const float* __restrict__ W4, const float* __restrict__ b4,
    float* __restrict__ out)
{
    __shared__ float sx[HD];
    __shared__ float sred[H2];
    const int i = blockIdx.x, t = threadIdx.x;
    if (i == 0 && t == 0) g_cnt = 0;
    if (t < HD) sx[t] = x[i * HD + t];
    __syncthreads();

    float h = b3[t];
#pragma unroll
    for (int k = 0; k < HD; k++)
        h = fmaf(sx[k], W3[k * H2 + t], h);
    h = fmaxf(h, 0.f);

    sred[t] = h * W4[t];
    __syncthreads();
#pragma unroll
    for (int s = 64; s > 0; s >>= 1) {
        if (t < s) sred[t] += sred[t + s];
        __syncthreads();
    }
    if (t == 0) {
        float v = sred[0] + b4[0];
        out[i] = 1.0f / (1.0f + expf(-v));
    }
}

extern "C" void kernel_launch(void* const* d_in, const int* in_sizes, int n_in,
                              void* d_out, int out_size)
{
    const float* A   = (const float*)d_in[0];
    const float* x   = (const float*)d_in[1];
    const float* e   = (const float*)d_in[2];
    const float* W1a = (const float*)d_in[3];
    const float* b1a = (const float*)d_in[4];
    const float* W1b = (const float*)d_in[5];
    const float* b1b = (const float*)d_in[6];
    const float* W2a = (const float*)d_in[7];
    const float* b2a = (const float*)d_in[8];
    const float* W2b = (const float*)d_in[9];
    const float* b2b = (const float*)d_in[10];
    const float* W3  = (const float*)d_in[11];
    const float* b3  = (const float*)d_in[12];
    const float* W4  = (const float*)d_in[13];
    const float* b4  = (const float*)d_in[14];
    float* out = (float*)d_out;

    float *P, *Q, *X1, *X2;
    cudaGetSymbolAddress((void**)&P,  g_P);
    cudaGetSymbolAddress((void**)&Q,  g_Q);
    cudaGetSymbolAddress((void**)&X1, g_X1);
    cudaGetSymbolAddress((void**)&X2, g_X2);

    const int SMEM = (2048 + 4096 + 64 + 4 * HD * 32) * 4;   // 57600 B
    cudaFuncSetAttribute(edge_kernel, cudaFuncAttributeMaxDynamicSharedMemorySize, SMEM);

    // Layer 1 (prep compacts A, computes P/Q, zeroes X1)
    prep_kernel<<<NN / 4, 256>>>(A, x, W1a, b1a, P, Q, X1);
    edge_kernel<<<EGRID, 256, SMEM>>>(e, P, Q, W1a, W1b, b1b, X1);
    // Layer 2 (no recompaction)
    prep_kernel<<<NN / 4, 256>>>(nullptr, X1, W2a, b2a, P, Q, X2);
    edge_kernel<<<EGRID, 256, SMEM>>>(e, P, Q, W2a, W2b, b2b, X2);
    // Head (also resets g_cnt)
    final_kernel<<<NN, H2>>>(X2, W3, b3, W4, b4, out);
}

// round 12
// speedup vs baseline: 2.6542x; 1.1479x over previous
#include <cuda_runtime.h>

#define NN 768
#define FD 64
#define DE 32
#define HD 64
#define H2 128
#define EGRID 296

typedef unsigned long long u64;

// Scratch (allocation-free rule: __device__ globals), 16B-aligned
__device__ __align__(16) float g_P [NN * HD];
__device__ __align__(16) float g_Q [NN * HD];
__device__ __align__(16) float g_X1[NN * HD];
__device__ __align__(16) float g_X2[NN * HD];
__device__ unsigned g_cnt;          // zero-init at load; reset by final_kernel
__device__ unsigned g_edges[NN * NN];

// ---- packed f32x2 helpers (sm_103a) ----
__device__ __forceinline__ u64 pack2(float lo, float hi) {
    u64 r; asm("mov.b64 %0, {%1, %2};" : "=l"(r) : "f"(lo), "f"(hi)); return r;
}
__device__ __forceinline__ void unpack2(u64 v, float& lo, float& hi) {
    asm("mov.b64 {%0, %1}, %2;" : "=f"(lo), "=f"(hi) : "l"(v));
}
__device__ __forceinline__ u64 ffma2(u64 a, u64 b, u64 c) {
    u64 d; asm("fma.rn.f32x2 %0, %1, %2, %3;" : "=l"(d) : "l"(a), "l"(b), "l"(c));
    return d;
}
__device__ __forceinline__ u64 fadd2(u64 a, u64 b) {
    u64 d; asm("add.rn.f32x2 %0, %1, %2;" : "=l"(d) : "l"(a), "l"(b)); return d;
}
__device__ __forceinline__ u64 relu2(u64 v) {
    float lo, hi; unpack2(v, lo, hi);
    return pack2(fmaxf(lo, 0.f), fmaxf(hi, 0.f));
}

// Fused prep: (optional) adjacency compaction + P/Q GEMMs + zero next accumulator.
__global__ __launch_bounds__(256) void prep_kernel(
    const float* __restrict__ A,   // null => skip compaction
    const float* __restrict__ x, const float* __restrict__ W,
    const float* __restrict__ ba, float* __restrict__ P,
    float* __restrict__ Q, float* __restrict__ Xz)
{
    __shared__ float sW[2 * FD * HD];   // 32 KB
    __shared__ float sx[4][FD];
    __shared__ unsigned lcnt[4], lbase[4];

    const int tid = threadIdx.x;
    const int b   = blockIdx.x;
    const int nl  = tid >> 6;
    const int h   = tid & 63;
    const int node = b * 4 + nl;

    {
        unsigned g = b * 256u + (unsigned)tid;
        if (g < (NN * HD) / 4) ((float4*)Xz)[g] = make_float4(0.f, 0.f, 0.f, 0.f);
    }

    if (tid < 4) lcnt[tid] = 0;
#pragma unroll
    for (int k = 0; k < 8; k++)
        ((float4*)sW)[tid + k * 256] = ((const float4*)W)[tid + k * 256];
    sx[nl][h] = x[node * FD + h];
    __syncthreads();

    unsigned myj[4][3]; int mc[4]; unsigned mpos[4];
    if (A) {
#pragma unroll
        for (int r = 0; r < 4; r++) {
            mc[r] = 0;
            const float* Ar = A + (size_t)(b * 4 + r) * NN;
#pragma unroll
            for (int t = 0; t < 3; t++) {
                int j = tid + t * 256;
                if (Ar[j] != 0.0f) myj[r][mc[r]++] = (unsigned)j;
            }
            mpos[r] = mc[r] ? atomicAdd(&lcnt[r], (unsigned)mc[r]) : 0u;
        }
    }

    float p = ba[h], q = 0.f;
#pragma unroll
    for (int f = 0; f < FD; f++) {
        float xv = sx[nl][f];
        float wi = sW[f * HD + h];
        float wd = sW[(FD + f) * HD + h];
        p = fmaf(xv, wi - wd, p);
        q = fmaf(xv, wd, q);
    }
    P[node * HD + h] = p;
    Q[node * HD + h] = q;

    if (A) {
        __syncthreads();
        if (tid == 0) {
#pragma unroll
            for (int r = 0; r < 4; r++)
                lbase[r] = atomicAdd(&g_cnt, lcnt[r]);
        }
        __syncthreads();
#pragma unroll
        for (int r = 0; r < 4; r++) {
            unsigned base = lbase[r] + mpos[r];
            unsigned rowbits = (unsigned)(b * 4 + r) << 10;
            for (int t = 0; t < mc[r]; t++)
                g_edges[base + t] = rowbits | myj[r][t];
        }
    }
}

// Warp-pair per 32-edge batch; BOTH layers in the 4-edge x 8-h lane tile.
// e-rows staged per-warp [de][edge] (conflict-free); all weight LDS divergent
// or small-broadcast; z exchanged via pair tile [k][edge]; fused atomics.
__global__ __launch_bounds__(256, 2) void edge_kernel(
    const float* __restrict__ e,  const float* __restrict__ P,
    const float* __restrict__ Q,  const float* __restrict__ W,
    const float* __restrict__ Wb, const float* __restrict__ bb,
    float* __restrict__ out)
{
    extern __shared__ float sm[];
    float* sWe = sm;               // 2048
    float* sWb = sm + 2048;        // 4096
    float* sbb = sm + 6144;        // 64
    float* zx  = sm + 6208;        // 4 pairs * [64][32] = 8192
    float* esx = sm + 14400;       // 8 warps * [32][32] = 8192
    // total 22592 floats = 90368 B

    const int tid  = threadIdx.x;
    const int lane = tid & 31;
    const int warp = tid >> 5;
    const int pib  = warp >> 1;        // pair in block (0..3)
    const int hh   = warp & 1;         // h-half
    const int hbase = hh * 32;
    const int barid = 1 + pib;
    const int eg   = lane >> 2;        // edge group of 4 (0..7)
    const int hg   = lane & 3;         // h group of 8 / own e4 slot
    const int hoff = hbase + hg * 8;

    const unsigned cnt  = g_cnt;
    const unsigned nbat = (cnt + 31u) >> 5;
    const unsigned pairG  = (unsigned)pib * gridDim.x + blockIdx.x;
    const unsigned npairs = gridDim.x * 4u;
    float* zs = zx  + pib * (HD * 32);   // [k][edge] pair tile
    float* es = esx + warp * (DE * 32);  // [de][edge] own-warp tile

    // ---- prefetch first batch (overlaps weight staging) ----
    unsigned bat = pairG;
    bool have = bat < nbat;
    u64 pq2[16];         // becomes layer-a accumulator (tile 4e x 8h, h-packed)
    float ev[DE];        // own edge's e-row
    int iarr[4];
    if (have) {
        const unsigned ebase = bat * 32u + (unsigned)(eg * 4);
        uint4 pks = *(const uint4*)(g_edges + ebase);
        unsigned pkarr[4] = {pks.x, pks.y, pks.z, pks.w};
        int jown = 0;
#pragma unroll
        for (int e4 = 0; e4 < 4; e4++) {
            int ii = min((int)(pkarr[e4] >> 10), NN - 1);
            int jj = min((int)(pkarr[e4] & 1023u), NN - 1);
            iarr[e4] = ii;
            if (e4 == hg) jown = jj;
            const ulonglong2* Pp = (const ulonglong2*)(P + ii * HD + hoff);
            const ulonglong2* Qp = (const ulonglong2*)(Q + jj * HD + hoff);
            ulonglong2 p0 = Pp[0], p1 = Pp[1], q0 = Qp[0], q1 = Qp[1];
            pq2[e4 * 4 + 0] = fadd2(p0.x, q0.x);
            pq2[e4 * 4 + 1] = fadd2(p0.y, q0.y);
            pq2[e4 * 4 + 2] = fadd2(p1.x, q1.x);
            pq2[e4 * 4 + 3] = fadd2(p1.y, q1.y);
        }
        const int iown = iarr[hg];
        const float4* epp = (const float4*)(e + (size_t)(iown * NN + jown) * DE);
#pragma unroll
        for (int q4 = 0; q4 < 8; q4++) {
            float4 v = epp[q4];
            ev[q4 * 4 + 0] = v.x; ev[q4 * 4 + 1] = v.y;
            ev[q4 * 4 + 2] = v.z; ev[q4 * 4 + 3] = v.w;
        }
    }

    // ---- weight staging ----
    {
        const float4* Wg = (const float4*)(W + (2 * FD) * HD);
        ((float4*)sWe)[tid]       = Wg[tid];
        ((float4*)sWe)[tid + 256] = Wg[tid + 256];
        const float4* Wbg = (const float4*)Wb;
#pragma unroll
        for (int k = 0; k < 4; k++)
            ((float4*)sWb)[tid + k * 256] = Wbg[tid + k * 256];
        if (tid < HD) sbb[tid] = bb[tid];
    }
    __syncthreads();

    while (have) {
        // stage own edge's e-row: es[de][edge=lane] (conflict-free cols)
#pragma unroll
        for (int t = 0; t < DE; t++) es[t * 32 + lane] = ev[t];
        __syncwarp();

        // ---- layer a in the tile: z2t[e4*4+c] covers h (hoff+2c, +1) ----
        u64* z2t = pq2;   // accumulate in place
#pragma unroll
        for (int de = 0; de < DE; de++) {
            float4 e4v = *(const float4*)(es + de * 32 + eg * 4);
            const ulonglong2* wp = (const ulonglong2*)(sWe + de * HD + hoff);
            ulonglong2 wA = wp[0], wB = wp[1];
            u64 zd;
            zd = pack2(e4v.x, e4v.x);
            z2t[0]  = ffma2(zd, wA.x, z2t[0]);  z2t[1]  = ffma2(zd, wA.y, z2t[1]);
            z2t[2]  = ffma2(zd, wB.x, z2t[2]);  z2t[3]  = ffma2(zd, wB.y, z2t[3]);
            zd = pack2(e4v.y, e4v.y);
            z2t[4]  = ffma2(zd, wA.x, z2t[4]);  z2t[5]  = ffma2(zd, wA.y, z2t[5]);
            z2t[6]  = ffma2(zd, wB.x, z2t[6]);  z2t[7]  = ffma2(zd, wB.y, z2t[7]);
            zd = pack2(e4v.z, e4v.z);
            z2t[8]  = ffma2(zd, wA.x, z2t[8]);  z2t[9]  = ffma2(zd, wA.y, z2t[9]);
            z2t[10] = ffma2(zd, wB.x, z2t[10]); z2t[11] = ffma2(zd, wB.y, z2t[11]);
            zd = pack2(e4v.w, e4v.w);
            z2t[12] = ffma2(zd, wA.x, z2t[12]); z2t[13] = ffma2(zd, wA.y, z2t[13]);
            z2t[14] = ffma2(zd, wB.x, z2t[14]); z2t[15] = ffma2(zd, wB.y, z2t[15]);
        }

        // relu + stage z to pair tile [k][edge]
#pragma unroll
        for (int e4 = 0; e4 < 4; e4++) {
#pragma unroll
            for (int c = 0; c < 4; c++) {
                float lo, hi; unpack2(z2t[e4 * 4 + c], lo, hi);
                zs[(hoff + 2 * c + 0) * 32 + eg * 4 + e4] = fmaxf(lo, 0.f);
                zs[(hoff + 2 * c + 1) * 32 + eg * 4 + e4] = fmaxf(hi, 0.f);
            }
        }
        asm volatile("bar.sync %0, 64;" :: "r"(barid) : "memory");

        // ---- layer b (4 edges x 8 h tile) ----
        u64 m2[16];
        {
            const ulonglong2* bp = (const ulonglong2*)(sbb + hoff);
            ulonglong2 b0 = bp[0], b1 = bp[1];
#pragma unroll
            for (int e4 = 0; e4 < 4; e4++) {
                m2[e4 * 4 + 0] = b0.x; m2[e4 * 4 + 1] = b0.y;
                m2[e4 * 4 + 2] = b1.x; m2[e4 * 4 + 3] = b1.y;
            }
        }
#pragma unroll 8
        for (int k = 0; k < HD; k++) {
            float4 z4 = *(const float4*)(zs + k * 32 + eg * 4);
            const ulonglong2* wp = (const ulonglong2*)(sWb + k * HD + hoff);
            ulonglong2 wA = wp[0], wB = wp[1];
            u64 zd;
            zd = pack2(z4.x, z4.x);
            m2[0]  = ffma2(zd, wA.x, m2[0]);  m2[1]  = ffma2(zd, wA.y, m2[1]);
            m2[2]  = ffma2(zd, wB.x, m2[2]);  m2[3]  = ffma2(zd, wB.y, m2[3]);
            zd = pack2(z4.y, z4.y);
            m2[4]  = ffma2(zd, wA.x, m2[4]);  m2[5]  = ffma2(zd, wA.y, m2[5]);
            m2[6]  = ffma2(zd, wB.x, m2[6]);  m2[7]  = ffma2(zd, wB.y, m2[7]);
            zd = pack2(z4.z, z4.z);
            m2[8]  = ffma2(zd, wA.x, m2[8]);  m2[9]  = ffma2(zd, wA.y, m2[9]);
            m2[10] = ffma2(zd, wB.x, m2[10]); m2[11] = ffma2(zd, wB.y, m2[11]);
            zd = pack2(z4.w, z4.w);
            m2[12] = ffma2(zd, wA.x, m2[12]); m2[13] = ffma2(zd, wA.y, m2[13]);
            m2[14] = ffma2(zd, wB.x, m2[14]); m2[15] = ffma2(zd, wB.y, m2[15]);
        }

        // relu each edge's output, then scatter (fused when 4 edges share row i)
#pragma unroll
        for (int c = 0; c < 16; c++) m2[c] = relu2(m2[c]);

        const unsigned ebase = bat * 32u + (unsigned)(eg * 4);
        const bool fuse = (iarr[0] == iarr[1]) & (iarr[1] == iarr[2]) &
                          (iarr[2] == iarr[3]) & (ebase + 3u < cnt);
        if (fuse) {
            float4* op = (float4*)(out + iarr[0] * HD + hoff);
#pragma unroll
            for (int c = 0; c < 4; c++)
                m2[c] = fadd2(fadd2(m2[c], m2[4 + c]), fadd2(m2[8 + c], m2[12 + c]));
            float a0, a1, a2, a3;
            unpack2(m2[0], a0, a1); unpack2(m2[1], a2, a3);
            atomicAdd(op,     make_float4(a0, a1, a2, a3));
            unpack2(m2[2], a0, a1); unpack2(m2[3], a2, a3);
            atomicAdd(op + 1, make_float4(a0, a1, a2, a3));
        } else {
#pragma unroll
            for (int e4 = 0; e4 < 4; e4++) {
                if (ebase + (unsigned)e4 < cnt) {
                    float4* op = (float4*)(out + iarr[e4] * HD + hoff);
                    float a0, a1, a2, a3;
                    unpack2(m2[e4 * 4 + 0], a0, a1);
                    unpack2(m2[e4 * 4 + 1], a2, a3);
                    atomicAdd(op,     make_float4(a0, a1, a2, a3));
                    unpack2(m2[e4 * 4 + 2], a0, a1);
                    unpack2(m2[e4 * 4 + 3], a2, a3);
                    atomicAdd(op + 1, make_float4(a0, a1, a2, a3));
                }
            }
        }

        // ---- advance (rare: >1 task per pair) ----
        bat += npairs;
        have = bat < nbat;
        if (have) {
            asm volatile("bar.sync %0, 64;" :: "r"(barid) : "memory");
            const unsigned eb2 = bat * 32u + (unsigned)(eg * 4);
            uint4 pks = *(const uint4*)(g_edges + eb2);
            unsigned pkarr[4] = {pks.x, pks.y, pks.z, pks.w};
            int jown = 0;
#pragma unroll
            for (int e4 = 0; e4 < 4; e4++) {
                int ii = min((int)(pkarr[e4] >> 10), NN - 1);
                int jj = min((int)(pkarr[e4] & 1023u), NN - 1);
                iarr[e4] = ii;
                if (e4 == hg) jown = jj;
                const ulonglong2* Pp = (const ulonglong2*)(P + ii * HD + hoff);
                const ulonglong2* Qp = (const ulonglong2*)(Q + jj * HD + hoff);
                ulonglong2 p0 = Pp[0], p1 = Pp[1], q0 = Qp[0], q1 = Qp[1];
                pq2[e4 * 4 + 0] = fadd2(p0.x, q0.x);
                pq2[e4 * 4 + 1] = fadd2(p0.y, q0.y);
                pq2[e4 * 4 + 2] = fadd2(p1.x, q1.x);
                pq2[e4 * 4 + 3] = fadd2(p1.y, q1.y);
            }
            const int iown = iarr[hg];
            const float4* epp = (const float4*)(e + (size_t)(iown * NN + jown) * DE);
#pragma unroll
            for (int q4 = 0; q4 < 8; q4++) {
                float4 v = epp[q4];
                ev[q4 * 4 + 0] = v.x; ev[q4 * 4 + 1] = v.y;
                ev[q4 * 4 + 2] = v.z; ev[q4 * 4 + 3] = v.w;
            }
        }
    }
}

// out[i] = sigmoid( relu(x2_i @ W3 + b3) @ W4 + b4 ); resets g_cnt (runs last).
__global__ __launch_bounds__(128) void final_kernel(
    const float* __restrict__ x,
    const float* __restrict__ W3, const float* __restrict__ b3,
    const float* __restrict__ W4, const float* __restrict__ b4,
    float* __restrict__ out)
{
    __shared__ float sx[HD];
    __shared__ float sred[H2];
    const int i = blockIdx.x, t = threadIdx.x;
    if (i == 0 && t == 0) g_cnt = 0;
    if (t < HD) sx[t] = x[i * HD + t];
    __syncthreads();

    float h = b3[t];
#pragma unroll
    for (int k = 0; k < HD; k++)
        h = fmaf(sx[k], W3[k * H2 + t], h);
    h = fmaxf(h, 0.f);

    sred[t] = h * W4[t];
    __syncthreads();
#pragma unroll
    for (int s = 64; s > 0; s >>= 1) {
        if (t < s) sred[t] += sred[t + s];
        __syncthreads();
    }
    if (t == 0) {
        float v = sred[0] + b4[0];
        out[i] = 1.0f / (1.0f + expf(-v));
    }
}

extern "C" void kernel_launch(void* const* d_in, const int* in_sizes, int n_in,
                              void* d_out, int out_size)
{
    const float* A   = (const float*)d_in[0];
    const float* x   = (const float*)d_in[1];
    const float* e   = (const float*)d_in[2];
    const float* W1a = (const float*)d_in[3];
    const float* b1a = (const float*)d_in[4];
    const float* W1b = (const float*)d_in[5];
    const float* b1b = (const float*)d_in[6];
    const float* W2a = (const float*)d_in[7];
    const float* b2a = (const float*)d_in[8];
    const float* W2b = (const float*)d_in[9];
    const float* b2b = (const float*)d_in[10];
    const float* W3  = (const float*)d_in[11];
    const float* b3  = (const float*)d_in[12];
    const float* W4  = (const float*)d_in[13];
    const float* b4  = (const float*)d_in[14];
    float* out = (float*)d_out;

    float *P, *Q, *X1, *X2;
    cudaGetSymbolAddress((void**)&P,  g_P);
    cudaGetSymbolAddress((void**)&Q,  g_Q);
    cudaGetSymbolAddress((void**)&X1, g_X1);
    cudaGetSymbolAddress((void**)&X2, g_X2);

    const int SMEM = (2048 + 4096 + 64 + 4 * HD * 32 + 8 * DE * 32) * 4;  // 90368 B
    cudaFuncSetAttribute(edge_kernel, cudaFuncAttributeMaxDynamicSharedMemorySize, SMEM);

    // Layer 1 (prep compacts A, computes P/Q, zeroes X1)
    prep_kernel<<<NN / 4, 256>>>(A, x, W1a, b1a, P, Q, X1);
    edge_kernel<<<EGRID, 256, SMEM>>>(e, P, Q, W1a, W1b, b1b, X1);
    // Layer 2 (no recompaction)
    prep_kernel<<<NN / 4, 256>>>(nullptr, X1, W2a, b2a, P, Q, X2);
    edge_kernel<<<EGRID, 256, SMEM>>>(e, P, Q, W2a, W2b, b2b, X2);
    // Head (also resets g_cnt)
    final_kernel<<<NN, H2>>>(X2, W3, b3, W4, b4, out);
}